// round 15
// baseline (speedup 1.0000x reference)
#include <cuda_runtime.h>
#include <cuda_fp16.h>
#include <math.h>
#include <stdint.h>

#define NROWS 16384   // B*T
#define E     512
#define H     8
#define BN_EPS 1e-5f
#define GAMMA  1.5f
#define SCALE_S 32.0f
#define INV_S   (1.0f / 32.0f)

#define BM 128
#define BN 128
#define BK 64
#define NSTAGE 3
#define NMT   (NROWS / BM)            // 128 m-tiles
#define TILE_B (BM * BK * 2)          // 16384 bytes per tile (128B rows)
#define STAGE_B (4 * TILE_B)          // 65536 (xh, xs, wh, ws)
#define SMEM_TOTAL (NSTAGE * STAGE_B) // 196608 (192 KB)

#define XSPLIT_BLOCKS (NROWS * E / 4 / 256)   // 8192
#define WSPLIT_BLOCKS (H * E * E / 4 / 256)   // 2048

// ---------------- static device scratch (no allocation) ----------------
__device__ float g_logits[(size_t)H * NROWS * E];   // 268 MB
__device__ float g_psum[(size_t)H * NMT * E];
__device__ float g_psq [(size_t)H * NMT * E];
__device__ float g_scale[H * E];
__device__ float g_shift[H * E];
__device__ __half g_xh[(size_t)NROWS * E];   // fp16(x)
__device__ __half g_xs[(size_t)NROWS * E];   // fp16(xh + s*(x-xh))
__device__ __half g_wh[(size_t)H * E * E];
__device__ __half g_ws[(size_t)H * E * E];

// ---------------- PTX helpers ----------------
static __device__ __forceinline__ uint32_t smem_u32(const void* p) {
    uint32_t a;
    asm("{ .reg .u64 t; cvta.to.shared.u64 t, %1; cvt.u32.u64 %0, t; }" : "=r"(a) : "l"(p));
    return a;
}
static __device__ __forceinline__ void cp_async16(uint32_t dst, const void* src) {
    asm volatile("cp.async.cg.shared.global [%0], [%1], 16;" :: "r"(dst), "l"(src) : "memory");
}
static __device__ __forceinline__ void cp_commit() {
    asm volatile("cp.async.commit_group;" ::: "memory");
}
template <int N>
static __device__ __forceinline__ void cp_wait() {
    asm volatile("cp.async.wait_group %0;" :: "n"(N) : "memory");
}
static __device__ __forceinline__ void ldsm4(uint32_t* r, uint32_t addr) {
    asm volatile("ldmatrix.sync.aligned.m8n8.x4.shared.b16 {%0,%1,%2,%3}, [%4];"
                 : "=r"(r[0]), "=r"(r[1]), "=r"(r[2]), "=r"(r[3]) : "r"(addr));
}
static __device__ __forceinline__ void mma16816(float* d, const uint32_t* a, const uint32_t* b) {
    asm volatile(
        "mma.sync.aligned.m16n8k16.row.col.f32.f16.f16.f32 "
        "{%0,%1,%2,%3}, {%4,%5,%6,%7}, {%8,%9}, {%0,%1,%2,%3};"
        : "+f"(d[0]), "+f"(d[1]), "+f"(d[2]), "+f"(d[3])
        : "r"(a[0]), "r"(a[1]), "r"(a[2]), "r"(a[3]), "r"(b[0]), "r"(b[1]));
}

// 128B-row SW128 swizzle: 16B chunk c of row r stored at chunk (c ^ (r&7))
static __device__ __forceinline__ uint32_t swz(int row, int ch) {
    return (uint32_t)((row << 7) + (((ch ^ row) & 7) << 4));
}

// ---------------------------------------------------------------------------
// fused split kernel: h = fp16(v), s-variant = fp16(float(h) + S*(v-float(h)))
// blocks [0, XSPLIT_BLOCKS) process x; the rest process W.
// ---------------------------------------------------------------------------
static __device__ __forceinline__ void split4s(const float4 v, __half* hp, __half* sp, size_t i) {
    float a[4] = {v.x, v.y, v.z, v.w};
    uint32_t ph[2], ps[2];
    #pragma unroll
    for (int p = 0; p < 2; p++) {
        __half h0 = __float2half_rn(a[2*p+0]);
        __half h1 = __float2half_rn(a[2*p+1]);
        float f0 = __half2float(h0), f1 = __half2float(h1);
        __half s0 = __float2half_rn(fmaf(SCALE_S, a[2*p+0] - f0, f0));
        __half s1 = __float2half_rn(fmaf(SCALE_S, a[2*p+1] - f1, f1));
        ph[p] = ((uint32_t)__half_as_ushort(h1) << 16) | __half_as_ushort(h0);
        ps[p] = ((uint32_t)__half_as_ushort(s1) << 16) | __half_as_ushort(s0);
    }
    *(uint2*)(hp + i) = make_uint2(ph[0], ph[1]);
    *(uint2*)(sp + i) = make_uint2(ps[0], ps[1]);
}
__global__ void __launch_bounds__(256) split_kernel(const float* __restrict__ x,
                                                    const float* __restrict__ w) {
    if (blockIdx.x < XSPLIT_BLOCKS) {
        size_t i = ((size_t)blockIdx.x * 256 + threadIdx.x) * 4;
        split4s(*(const float4*)(x + i), g_xh, g_xs, i);
    } else {
        size_t i = ((size_t)(blockIdx.x - XSPLIT_BLOCKS) * 256 + threadIdx.x) * 4;
        split4s(*(const float4*)(w + i), g_wh, g_ws, i);
    }
}

// ---------------------------------------------------------------------------
// HMMA GEMM + fused BN partial stats, amplified-residual 2-product scheme:
//   P1 = xh*wh,  P2 = xs*ws,  logits = P1 + (P2 - P1)/S
// CTA 128x128, BK=64, 3-stage cp.async (192 KB), 8 warps (2M x 4N),
// warp tile 64x32: lowest ldsm/MMA ratio + fewest stage barriers.
// ---------------------------------------------------------------------------
__global__ void __launch_bounds__(256) gemm_kernel() {
    extern __shared__ __align__(1024) char smem[];
    const uint32_t sb = smem_u32(smem);
    const int tid  = threadIdx.x;
    const int lane = tid & 31;
    const int wid  = tid >> 5;
    const int wm   = wid & 1;      // 2 warps along M (64 rows each)
    const int wn   = wid >> 1;     // 4 warps along N (32 cols each)
    const int bm   = blockIdx.x;
    const int m0   = bm * BM;
    const int o0   = blockIdx.y * BN;
    const int h    = blockIdx.z;

    const __half* gxh = g_xh + (size_t)m0 * E;
    const __half* gxs = g_xs + (size_t)m0 * E;
    const __half* gwh = g_wh + ((size_t)h * E + o0) * E;
    const __half* gws = g_ws + ((size_t)h * E + o0) * E;

    const int trow = tid >> 3;   // 0..31
    const int tc   = tid & 7;    // 16B chunk 0..7

    float C1[4][4][4], C2[4][4][4];
    #pragma unroll
    for (int i = 0; i < 4; i++)
        #pragma unroll
        for (int j = 0; j < 4; j++)
            #pragma unroll
            for (int k = 0; k < 4; k++) { C1[i][j][k] = 0.f; C2[i][j][k] = 0.f; }

    auto load_stage = [&](int s, int k0) {
        const uint32_t base = sb + s * STAGE_B;
        #pragma unroll
        for (int i = 0; i < 4; i++) {
            const int row = trow + i * 32;
            const uint32_t o = swz(row, tc);
            const size_t go = (size_t)row * E + (size_t)k0 + tc * 8;
            cp_async16(base + o,              gxh + go);
            cp_async16(base + TILE_B + o,     gxs + go);
            cp_async16(base + 2 * TILE_B + o, gwh + go);
            cp_async16(base + 3 * TILE_B + o, gws + go);
        }
    };

    auto compute_stage = [&](int s) {
        const uint32_t aHB = sb + s * STAGE_B;
        const uint32_t aSB = aHB + TILE_B;
        const uint32_t bHB = aHB + 2 * TILE_B;
        const uint32_t bSB = aHB + 3 * TILE_B;
        #pragma unroll
        for (int ks = 0; ks < 4; ks++) {
            uint32_t a[4][4], b1[4][2], b2[4][2];
            const int arow = wm * 64 + (lane & 15);
            const int ach  = ks * 2 + (lane >> 4);
            #pragma unroll
            for (int p = 0; p < 2; p++) {
                const int row = wn * 32 + p * 16 + (lane & 7) + ((lane >> 4) << 3);
                const int ch  = ks * 2 + ((lane >> 3) & 1);
                uint32_t r[4];
                ldsm4(r, bHB + swz(row, ch));
                b1[2*p][0] = r[0];   b1[2*p][1] = r[1];
                b1[2*p+1][0] = r[2]; b1[2*p+1][1] = r[3];
                ldsm4(r, bSB + swz(row, ch));
                b2[2*p][0] = r[0];   b2[2*p][1] = r[1];
                b2[2*p+1][0] = r[2]; b2[2*p+1][1] = r[3];
            }
            // P1: xh * wh
            #pragma unroll
            for (int mi = 0; mi < 4; mi++)
                ldsm4(a[mi], aHB + swz(arow + mi * 16, ach));
            #pragma unroll
            for (int mi = 0; mi < 4; mi++)
                #pragma unroll
                for (int nj = 0; nj < 4; nj++)
                    mma16816(C1[mi][nj], a[mi], b1[nj]);
            // P2: xs * ws (overwrite a-frags)
            #pragma unroll
            for (int mi = 0; mi < 4; mi++)
                ldsm4(a[mi], aSB + swz(arow + mi * 16, ach));
            #pragma unroll
            for (int mi = 0; mi < 4; mi++)
                #pragma unroll
                for (int nj = 0; nj < 4; nj++)
                    mma16816(C2[mi][nj], a[mi], b2[nj]);
        }
    };

    load_stage(0, 0); cp_commit();
    load_stage(1, BK); cp_commit();

    int ls = 2, cs = 0;
    #pragma unroll 1
    for (int c = 0; c < E / BK; c++) {
        cp_wait<1>();
        __syncthreads();
        if (c + 2 < E / BK) load_stage(ls, (c + 2) * BK);
        cp_commit();
        compute_stage(cs);
        ls = (ls == NSTAGE - 1) ? 0 : ls + 1;
        cs = (cs == NSTAGE - 1) ? 0 : cs + 1;
    }

    // merge: C = P1 + (P2 - P1)/S
    #pragma unroll
    for (int mi = 0; mi < 4; mi++)
        #pragma unroll
        for (int nj = 0; nj < 4; nj++)
            #pragma unroll
            for (int k = 0; k < 4; k++)
                C1[mi][nj][k] = fmaf(INV_S, C2[mi][nj][k] - C1[mi][nj][k], C1[mi][nj][k]);

    // ---- epilogue: store logits + per-CTA column stats ----
    float* Cg = g_logits + (size_t)h * NROWS * E;
    const int rb = m0 + wm * 64;
    const int cb = o0 + wn * 32;
    #pragma unroll
    for (int mi = 0; mi < 4; mi++) {
        const int r = rb + mi * 16 + (lane >> 2);
        #pragma unroll
        for (int nj = 0; nj < 4; nj++) {
            const int col = cb + nj * 8 + 2 * (lane & 3);
            __stcs((float2*)(Cg + (size_t)r * E + col),       make_float2(C1[mi][nj][0], C1[mi][nj][1]));
            __stcs((float2*)(Cg + (size_t)(r + 8) * E + col), make_float2(C1[mi][nj][2], C1[mi][nj][3]));
        }
    }

    // column partial sums over this CTA's 128 rows (deterministic)
    float s[4][2], q[4][2];
    #pragma unroll
    for (int nj = 0; nj < 4; nj++) { s[nj][0] = s[nj][1] = q[nj][0] = q[nj][1] = 0.f; }
    #pragma unroll
    for (int mi = 0; mi < 4; mi++)
        #pragma unroll
        for (int nj = 0; nj < 4; nj++) {
            float v0 = C1[mi][nj][0], v1 = C1[mi][nj][1], v2 = C1[mi][nj][2], v3 = C1[mi][nj][3];
            s[nj][0] += v0 + v2; q[nj][0] += v0 * v0 + v2 * v2;
            s[nj][1] += v1 + v3; q[nj][1] += v1 * v1 + v3 * v3;
        }
    #pragma unroll
    for (int off = 4; off < 32; off <<= 1)
        #pragma unroll
        for (int nj = 0; nj < 4; nj++) {
            s[nj][0] += __shfl_xor_sync(0xffffffffu, s[nj][0], off);
            s[nj][1] += __shfl_xor_sync(0xffffffffu, s[nj][1], off);
            q[nj][0] += __shfl_xor_sync(0xffffffffu, q[nj][0], off);
            q[nj][1] += __shfl_xor_sync(0xffffffffu, q[nj][1], off);
        }

    __syncthreads();                      // done reading tiles; reuse smem
    float* red = (float*)smem;            // [2(wm)][128(col)][2(stat)]
    if (lane < 4) {
        #pragma unroll
        for (int nj = 0; nj < 4; nj++)
            #pragma unroll
            for (int e = 0; e < 2; e++) {
                const int col = wn * 32 + nj * 8 + 2 * lane + e;
                red[(wm * 128 + col) * 2 + 0] = s[nj][e];
                red[(wm * 128 + col) * 2 + 1] = q[nj][e];
            }
    }
    __syncthreads();
    {
        const int col = tid >> 1;
        const int st  = tid & 1;
        const float v = red[(0 * 128 + col) * 2 + st] + red[(1 * 128 + col) * 2 + st];
        float* dst = st ? g_psq : g_psum;
        dst[((size_t)h * NMT + bm) * E + o0 + col] = v;
    }
}

// ---------------------------------------------------------------------------
// finalize: reduce NMT partials -> scale/shift.
// grid (H,4) x 512: block owns 128 o-cols; 4 thread-groups each sum 32 chunks.
// ---------------------------------------------------------------------------
__global__ void __launch_bounds__(512) finalize_kernel(const float* __restrict__ bw,
                                                       const float* __restrict__ bb) {
    __shared__ float sred[4][128][2];
    const int h    = blockIdx.x;
    const int o    = blockIdx.y * 128 + (threadIdx.x & 127);
    const int part = threadIdx.x >> 7;          // 0..3
    const float* ps = g_psum + (size_t)h * NMT * E + o;
    const float* pq = g_psq  + (size_t)h * NMT * E + o;
    float s = 0.f, s2 = 0.f;
    #pragma unroll 8
    for (int c = part * 32; c < part * 32 + 32; c++) {
        s  += ps[(size_t)c * E];
        s2 += pq[(size_t)c * E];
    }
    sred[part][threadIdx.x & 127][0] = s;
    sred[part][threadIdx.x & 127][1] = s2;
    __syncthreads();
    if (threadIdx.x < 128) {
        const int ol = threadIdx.x;
        float ts  = sred[0][ol][0] + sred[1][ol][0] + sred[2][ol][0] + sred[3][ol][0];
        float ts2 = sred[0][ol][1] + sred[1][ol][1] + sred[2][ol][1] + sred[3][ol][1];
        const float inv_n = 1.0f / (float)NROWS;
        float mean = ts * inv_n;
        float var  = fmaf(-mean, mean, ts2 * inv_n);
        float istd = rsqrtf(var + BN_EPS);
        const int og = blockIdx.y * 128 + ol;
        float sc   = bw[h * E + og] * istd;
        g_scale[h * E + og] = sc;
        g_shift[h * E + og] = fmaf(-mean, sc, bb[h * E + og]);
    }
}

// ---------------------------------------------------------------------------
// Sequential head scan with sparsemax (Newton tau), one warp per row.
// 128-thread blocks (4 warps) -> 5 blocks/SM at 98 regs = 20 warps/SM
// (vs 16 at 256-thread blocks): more outstanding memory per SM.
// Head h+1's logits prefetched before head h's Newton chain; streaming
// loads (read-once) and stores (never re-read).
// ---------------------------------------------------------------------------
__global__ void __launch_bounds__(128) scan_kernel(const float* __restrict__ x,
                                                   float* __restrict__ out_masked,
                                                   float* __restrict__ out_masks) {
    const int gw   = (blockIdx.x * blockDim.x + threadIdx.x) >> 5;
    const int lane = threadIdx.x & 31;
    if (gw >= NROWS) return;
    const int n = gw;
    const int b = n >> 9;
    const int t = n & 511;

    float xr[16], prior[16], lraw[16];
    const float* xp = x + (size_t)n * E;
    #pragma unroll
    for (int j = 0; j < 16; j++) {
        xr[j]    = __ldcs(xp + lane + 32 * j);
        prior[j] = 1.0f;
    }
    // preload head 0 logits
    {
        const float* Lp = g_logits + (size_t)n * E;
        #pragma unroll
        for (int j = 0; j < 16; j++) lraw[j] = __ldcs(Lp + lane + 32 * j);
    }

    for (int h = 0; h < H; h++) {
        const float* scp = g_scale + h * E;
        const float* shp = g_shift + h * E;

        float z[16];
        float m = -1e30f;
        #pragma unroll
        for (int j = 0; j < 16; j++) {
            const int o = lane + 32 * j;
            float v = fmaf(lraw[j], scp[o], shp[o]) * prior[j];
            z[j] = v;
            m = fmaxf(m, v);
        }
        // prefetch next head's logits; latency hides under Newton below
        if (h + 1 < H) {
            const float* Ln = g_logits + ((size_t)(h + 1) * NROWS + n) * E;
            #pragma unroll
            for (int j = 0; j < 16; j++) lraw[j] = __ldcs(Ln + lane + 32 * j);
        }
        #pragma unroll
        for (int off = 16; off; off >>= 1)
            m = fmaxf(m, __shfl_xor_sync(0xffffffffu, m, off));

        float tau = m - 1.0f;
        for (int it = 0; it < 64; it++) {
            float S = 0.f, K = 0.f;
            #pragma unroll
            for (int j = 0; j < 16; j++) {
                if (z[j] > tau) { S += z[j]; K += 1.0f; }
            }
            #pragma unroll
            for (int off = 16; off; off >>= 1) {
                S += __shfl_xor_sync(0xffffffffu, S, off);
                K += __shfl_xor_sync(0xffffffffu, K, off);
            }
            float tnew = (S - 1.0f) / K;
            if (!(tnew > tau)) break;
            tau = tnew;
        }

        float* om = out_masked + ((size_t)h * NROWS + n) * E;              // (H,B,T,E)
        float* ok = out_masks  + (((size_t)b * H + h) * 512 + t) * E;      // (B,H,T,E)
        #pragma unroll
        for (int j = 0; j < 16; j++) {
            const int o = lane + 32 * j;
            float mask = fmaxf(z[j] - tau, 0.0f);
            __stcs(om + o, xr[j] * mask);
            __stcs(ok + o, mask);
            prior[j] *= fmaxf(GAMMA - mask, 0.0f);
        }
    }
}

// ---------------------------------------------------------------------------
extern "C" void kernel_launch(void* const* d_in, const int* in_sizes, int n_in,
                              void* d_out, int out_size) {
    const float* x  = (const float*)d_in[0];
    const float* W  = (const float*)d_in[1];
    const float* bw = (const float*)d_in[2];
    const float* bb = (const float*)d_in[3];
    float* out_masked = (float*)d_out;                                  // (H,B,T,E)
    float* out_masks  = (float*)d_out + (size_t)H * NROWS * E;          // (B,H,T,E)

    cudaFuncSetAttribute(gemm_kernel, cudaFuncAttributeMaxDynamicSharedMemorySize, SMEM_TOTAL);

    split_kernel<<<XSPLIT_BLOCKS + WSPLIT_BLOCKS, 256>>>(x, W);

    dim3 ggrid(NROWS / BM, E / BN, H);
    gemm_kernel<<<ggrid, 256, SMEM_TOTAL>>>();

    finalize_kernel<<<dim3(H, 4), 512>>>(bw, bb);
    scan_kernel<<<NROWS / 4, 128>>>(x, out_masked, out_masks);
}

// round 16
// speedup vs baseline: 1.0067x; 1.0067x over previous
#include <cuda_runtime.h>
#include <cuda_fp16.h>
#include <math.h>
#include <stdint.h>

#define NROWS 16384   // B*T
#define E     512
#define H     8
#define BN_EPS 1e-5f
#define GAMMA  1.5f
#define SCALE_S 32.0f
#define INV_S   (1.0f / 32.0f)

#define BM 128
#define BN 128
#define BK 64
#define NSTAGE 3
#define NMT   (NROWS / BM)            // 128 m-tiles
#define TILE_B (BM * BK * 2)          // 16384 bytes per tile (128B rows)
#define STAGE_B (4 * TILE_B)          // 65536 (xh, xs, wh, ws)
#define SMEM_TOTAL (NSTAGE * STAGE_B) // 196608 (192 KB)

#define XSPLIT_BLOCKS (NROWS * E / 4 / 256)   // 8192
#define WSPLIT_BLOCKS (H * E * E / 4 / 256)   // 2048

// ---------------- static device scratch (no allocation) ----------------
__device__ float g_logits[(size_t)H * NROWS * E];   // 268 MB
__device__ float g_psum[(size_t)H * NMT * E];
__device__ float g_psq [(size_t)H * NMT * E];
__device__ float g_scale[H * E];
__device__ float g_shift[H * E];
__device__ __half g_xh[(size_t)NROWS * E];   // fp16(x)
__device__ __half g_xs[(size_t)NROWS * E];   // fp16(xh + s*(x-xh))
__device__ __half g_wh[(size_t)H * E * E];
__device__ __half g_ws[(size_t)H * E * E];

// ---------------- PTX helpers ----------------
static __device__ __forceinline__ uint32_t smem_u32(const void* p) {
    uint32_t a;
    asm("{ .reg .u64 t; cvta.to.shared.u64 t, %1; cvt.u32.u64 %0, t; }" : "=r"(a) : "l"(p));
    return a;
}
static __device__ __forceinline__ void cp_async16(uint32_t dst, const void* src) {
    asm volatile("cp.async.cg.shared.global [%0], [%1], 16;" :: "r"(dst), "l"(src) : "memory");
}
static __device__ __forceinline__ void cp_commit() {
    asm volatile("cp.async.commit_group;" ::: "memory");
}
template <int N>
static __device__ __forceinline__ void cp_wait() {
    asm volatile("cp.async.wait_group %0;" :: "n"(N) : "memory");
}
static __device__ __forceinline__ void ldsm4(uint32_t* r, uint32_t addr) {
    asm volatile("ldmatrix.sync.aligned.m8n8.x4.shared.b16 {%0,%1,%2,%3}, [%4];"
                 : "=r"(r[0]), "=r"(r[1]), "=r"(r[2]), "=r"(r[3]) : "r"(addr));
}
static __device__ __forceinline__ void mma16816(float* d, const uint32_t* a, const uint32_t* b) {
    asm volatile(
        "mma.sync.aligned.m16n8k16.row.col.f32.f16.f16.f32 "
        "{%0,%1,%2,%3}, {%4,%5,%6,%7}, {%8,%9}, {%0,%1,%2,%3};"
        : "+f"(d[0]), "+f"(d[1]), "+f"(d[2]), "+f"(d[3])
        : "r"(a[0]), "r"(a[1]), "r"(a[2]), "r"(a[3]), "r"(b[0]), "r"(b[1]));
}

// 128B-row SW128 swizzle: 16B chunk c of row r stored at chunk (c ^ (r&7))
static __device__ __forceinline__ uint32_t swz(int row, int ch) {
    return (uint32_t)((row << 7) + (((ch ^ row) & 7) << 4));
}

// ---------------------------------------------------------------------------
// fused split kernel: h = fp16(v), s-variant = fp16(float(h) + S*(v-float(h)))
// blocks [0, XSPLIT_BLOCKS) process x; the rest process W.
// ---------------------------------------------------------------------------
static __device__ __forceinline__ void split4s(const float4 v, __half* hp, __half* sp, size_t i) {
    float a[4] = {v.x, v.y, v.z, v.w};
    uint32_t ph[2], ps[2];
    #pragma unroll
    for (int p = 0; p < 2; p++) {
        __half h0 = __float2half_rn(a[2*p+0]);
        __half h1 = __float2half_rn(a[2*p+1]);
        float f0 = __half2float(h0), f1 = __half2float(h1);
        __half s0 = __float2half_rn(fmaf(SCALE_S, a[2*p+0] - f0, f0));
        __half s1 = __float2half_rn(fmaf(SCALE_S, a[2*p+1] - f1, f1));
        ph[p] = ((uint32_t)__half_as_ushort(h1) << 16) | __half_as_ushort(h0);
        ps[p] = ((uint32_t)__half_as_ushort(s1) << 16) | __half_as_ushort(s0);
    }
    *(uint2*)(hp + i) = make_uint2(ph[0], ph[1]);
    *(uint2*)(sp + i) = make_uint2(ps[0], ps[1]);
}
__global__ void __launch_bounds__(256) split_kernel(const float* __restrict__ x,
                                                    const float* __restrict__ w) {
    if (blockIdx.x < XSPLIT_BLOCKS) {
        size_t i = ((size_t)blockIdx.x * 256 + threadIdx.x) * 4;
        split4s(*(const float4*)(x + i), g_xh, g_xs, i);
    } else {
        size_t i = ((size_t)(blockIdx.x - XSPLIT_BLOCKS) * 256 + threadIdx.x) * 4;
        split4s(*(const float4*)(w + i), g_wh, g_ws, i);
    }
}

// ---------------------------------------------------------------------------
// HMMA GEMM + fused BN partial stats, amplified-residual 2-product scheme:
//   P1 = xh*wh,  P2 = xs*ws,  logits = P1 + (P2 - P1)/S
// CTA 128x128, BK=64, 3-stage cp.async (192 KB), 8 warps (2M x 4N),
// warp tile 64x32. Logits stored with DEFAULT policy so the tail of the
// write stream (late heads) stays L2-resident for the scan kernel.
// ---------------------------------------------------------------------------
__global__ void __launch_bounds__(256) gemm_kernel() {
    extern __shared__ __align__(1024) char smem[];
    const uint32_t sb = smem_u32(smem);
    const int tid  = threadIdx.x;
    const int lane = tid & 31;
    const int wid  = tid >> 5;
    const int wm   = wid & 1;      // 2 warps along M (64 rows each)
    const int wn   = wid >> 1;     // 4 warps along N (32 cols each)
    const int bm   = blockIdx.x;
    const int m0   = bm * BM;
    const int o0   = blockIdx.y * BN;
    const int h    = blockIdx.z;

    const __half* gxh = g_xh + (size_t)m0 * E;
    const __half* gxs = g_xs + (size_t)m0 * E;
    const __half* gwh = g_wh + ((size_t)h * E + o0) * E;
    const __half* gws = g_ws + ((size_t)h * E + o0) * E;

    const int trow = tid >> 3;   // 0..31
    const int tc   = tid & 7;    // 16B chunk 0..7

    float C1[4][4][4], C2[4][4][4];
    #pragma unroll
    for (int i = 0; i < 4; i++)
        #pragma unroll
        for (int j = 0; j < 4; j++)
            #pragma unroll
            for (int k = 0; k < 4; k++) { C1[i][j][k] = 0.f; C2[i][j][k] = 0.f; }

    auto load_stage = [&](int s, int k0) {
        const uint32_t base = sb + s * STAGE_B;
        #pragma unroll
        for (int i = 0; i < 4; i++) {
            const int row = trow + i * 32;
            const uint32_t o = swz(row, tc);
            const size_t go = (size_t)row * E + (size_t)k0 + tc * 8;
            cp_async16(base + o,              gxh + go);
            cp_async16(base + TILE_B + o,     gxs + go);
            cp_async16(base + 2 * TILE_B + o, gwh + go);
            cp_async16(base + 3 * TILE_B + o, gws + go);
        }
    };

    auto compute_stage = [&](int s) {
        const uint32_t aHB = sb + s * STAGE_B;
        const uint32_t aSB = aHB + TILE_B;
        const uint32_t bHB = aHB + 2 * TILE_B;
        const uint32_t bSB = aHB + 3 * TILE_B;
        #pragma unroll
        for (int ks = 0; ks < 4; ks++) {
            uint32_t a[4][4], b1[4][2], b2[4][2];
            const int arow = wm * 64 + (lane & 15);
            const int ach  = ks * 2 + (lane >> 4);
            #pragma unroll
            for (int p = 0; p < 2; p++) {
                const int row = wn * 32 + p * 16 + (lane & 7) + ((lane >> 4) << 3);
                const int ch  = ks * 2 + ((lane >> 3) & 1);
                uint32_t r[4];
                ldsm4(r, bHB + swz(row, ch));
                b1[2*p][0] = r[0];   b1[2*p][1] = r[1];
                b1[2*p+1][0] = r[2]; b1[2*p+1][1] = r[3];
                ldsm4(r, bSB + swz(row, ch));
                b2[2*p][0] = r[0];   b2[2*p][1] = r[1];
                b2[2*p+1][0] = r[2]; b2[2*p+1][1] = r[3];
            }
            // P1: xh * wh
            #pragma unroll
            for (int mi = 0; mi < 4; mi++)
                ldsm4(a[mi], aHB + swz(arow + mi * 16, ach));
            #pragma unroll
            for (int mi = 0; mi < 4; mi++)
                #pragma unroll
                for (int nj = 0; nj < 4; nj++)
                    mma16816(C1[mi][nj], a[mi], b1[nj]);
            // P2: xs * ws (overwrite a-frags)
            #pragma unroll
            for (int mi = 0; mi < 4; mi++)
                ldsm4(a[mi], aSB + swz(arow + mi * 16, ach));
            #pragma unroll
            for (int mi = 0; mi < 4; mi++)
                #pragma unroll
                for (int nj = 0; nj < 4; nj++)
                    mma16816(C2[mi][nj], a[mi], b2[nj]);
        }
    };

    load_stage(0, 0); cp_commit();
    load_stage(1, BK); cp_commit();

    int ls = 2, cs = 0;
    #pragma unroll 1
    for (int c = 0; c < E / BK; c++) {
        cp_wait<1>();
        __syncthreads();
        if (c + 2 < E / BK) load_stage(ls, (c + 2) * BK);
        cp_commit();
        compute_stage(cs);
        ls = (ls == NSTAGE - 1) ? 0 : ls + 1;
        cs = (cs == NSTAGE - 1) ? 0 : cs + 1;
    }

    // merge: C = P1 + (P2 - P1)/S
    #pragma unroll
    for (int mi = 0; mi < 4; mi++)
        #pragma unroll
        for (int nj = 0; nj < 4; nj++)
            #pragma unroll
            for (int k = 0; k < 4; k++)
                C1[mi][nj][k] = fmaf(INV_S, C2[mi][nj][k] - C1[mi][nj][k], C1[mi][nj][k]);

    // ---- epilogue: store logits (default policy) + per-CTA column stats ----
    float* Cg = g_logits + (size_t)h * NROWS * E;
    const int rb = m0 + wm * 64;
    const int cb = o0 + wn * 32;
    #pragma unroll
    for (int mi = 0; mi < 4; mi++) {
        const int r = rb + mi * 16 + (lane >> 2);
        #pragma unroll
        for (int nj = 0; nj < 4; nj++) {
            const int col = cb + nj * 8 + 2 * (lane & 3);
            *(float2*)(Cg + (size_t)r * E + col)       = make_float2(C1[mi][nj][0], C1[mi][nj][1]);
            *(float2*)(Cg + (size_t)(r + 8) * E + col) = make_float2(C1[mi][nj][2], C1[mi][nj][3]);
        }
    }

    // column partial sums over this CTA's 128 rows (deterministic)
    float s[4][2], q[4][2];
    #pragma unroll
    for (int nj = 0; nj < 4; nj++) { s[nj][0] = s[nj][1] = q[nj][0] = q[nj][1] = 0.f; }
    #pragma unroll
    for (int mi = 0; mi < 4; mi++)
        #pragma unroll
        for (int nj = 0; nj < 4; nj++) {
            float v0 = C1[mi][nj][0], v1 = C1[mi][nj][1], v2 = C1[mi][nj][2], v3 = C1[mi][nj][3];
            s[nj][0] += v0 + v2; q[nj][0] += v0 * v0 + v2 * v2;
            s[nj][1] += v1 + v3; q[nj][1] += v1 * v1 + v3 * v3;
        }
    #pragma unroll
    for (int off = 4; off < 32; off <<= 1)
        #pragma unroll
        for (int nj = 0; nj < 4; nj++) {
            s[nj][0] += __shfl_xor_sync(0xffffffffu, s[nj][0], off);
            s[nj][1] += __shfl_xor_sync(0xffffffffu, s[nj][1], off);
            q[nj][0] += __shfl_xor_sync(0xffffffffu, q[nj][0], off);
            q[nj][1] += __shfl_xor_sync(0xffffffffu, q[nj][1], off);
        }

    __syncthreads();                      // done reading tiles; reuse smem
    float* red = (float*)smem;            // [2(wm)][128(col)][2(stat)]
    if (lane < 4) {
        #pragma unroll
        for (int nj = 0; nj < 4; nj++)
            #pragma unroll
            for (int e = 0; e < 2; e++) {
                const int col = wn * 32 + nj * 8 + 2 * lane + e;
                red[(wm * 128 + col) * 2 + 0] = s[nj][e];
                red[(wm * 128 + col) * 2 + 1] = q[nj][e];
            }
    }
    __syncthreads();
    {
        const int col = tid >> 1;
        const int st  = tid & 1;
        const float v = red[(0 * 128 + col) * 2 + st] + red[(1 * 128 + col) * 2 + st];
        float* dst = st ? g_psq : g_psum;
        dst[((size_t)h * NMT + bm) * E + o0 + col] = v;
    }
}

// ---------------------------------------------------------------------------
// finalize: reduce NMT partials -> scale/shift.
// grid (H,4) x 512: block owns 128 o-cols; 4 thread-groups each sum 32 chunks.
// ---------------------------------------------------------------------------
__global__ void __launch_bounds__(512) finalize_kernel(const float* __restrict__ bw,
                                                       const float* __restrict__ bb) {
    __shared__ float sred[4][128][2];
    const int h    = blockIdx.x;
    const int o    = blockIdx.y * 128 + (threadIdx.x & 127);
    const int part = threadIdx.x >> 7;          // 0..3
    const float* ps = g_psum + (size_t)h * NMT * E + o;
    const float* pq = g_psq  + (size_t)h * NMT * E + o;
    float s = 0.f, s2 = 0.f;
    #pragma unroll 8
    for (int c = part * 32; c < part * 32 + 32; c++) {
        s  += ps[(size_t)c * E];
        s2 += pq[(size_t)c * E];
    }
    sred[part][threadIdx.x & 127][0] = s;
    sred[part][threadIdx.x & 127][1] = s2;
    __syncthreads();
    if (threadIdx.x < 128) {
        const int ol = threadIdx.x;
        float ts  = sred[0][ol][0] + sred[1][ol][0] + sred[2][ol][0] + sred[3][ol][0];
        float ts2 = sred[0][ol][1] + sred[1][ol][1] + sred[2][ol][1] + sred[3][ol][1];
        const float inv_n = 1.0f / (float)NROWS;
        float mean = ts * inv_n;
        float var  = fmaf(-mean, mean, ts2 * inv_n);
        float istd = rsqrtf(var + BN_EPS);
        const int og = blockIdx.y * 128 + ol;
        float sc   = bw[h * E + og] * istd;
        g_scale[h * E + og] = sc;
        g_shift[h * E + og] = fmaf(-mean, sc, bb[h * E + og]);
    }
}

// ---------------------------------------------------------------------------
// Sequential head scan with sparsemax (Newton tau), one warp per row.
// Warm-started Newton: tau0 = max(max(z)-1, (sum(z)-1)/E) — both lower
// bounds of tau*, the full-sum computed for free alongside the max.
// Head h+1's logits prefetched before head h's Newton chain; streaming
// reads (ldcs: read-once, no L2 pollution) and streaming output stores.
// ---------------------------------------------------------------------------
__global__ void __launch_bounds__(256) scan_kernel(const float* __restrict__ x,
                                                   float* __restrict__ out_masked,
                                                   float* __restrict__ out_masks) {
    const int gw   = (blockIdx.x * blockDim.x + threadIdx.x) >> 5;
    const int lane = threadIdx.x & 31;
    if (gw >= NROWS) return;
    const int n = gw;
    const int b = n >> 9;
    const int t = n & 511;

    float xr[16], prior[16], lraw[16];
    const float* xp = x + (size_t)n * E;
    #pragma unroll
    for (int j = 0; j < 16; j++) {
        xr[j]    = __ldcs(xp + lane + 32 * j);
        prior[j] = 1.0f;
    }
    // preload head 0 logits
    {
        const float* Lp = g_logits + (size_t)n * E;
        #pragma unroll
        for (int j = 0; j < 16; j++) lraw[j] = __ldcs(Lp + lane + 32 * j);
    }

    for (int h = 0; h < H; h++) {
        const float* scp = g_scale + h * E;
        const float* shp = g_shift + h * E;

        float z[16];
        float m = -1e30f;
        float zs = 0.f;
        #pragma unroll
        for (int j = 0; j < 16; j++) {
            const int o = lane + 32 * j;
            float v = fmaf(lraw[j], scp[o], shp[o]) * prior[j];
            z[j] = v;
            m  = fmaxf(m, v);
            zs += v;
        }
        // prefetch next head's logits; latency hides under Newton below
        if (h + 1 < H) {
            const float* Ln = g_logits + ((size_t)(h + 1) * NROWS + n) * E;
            #pragma unroll
            for (int j = 0; j < 16; j++) lraw[j] = __ldcs(Ln + lane + 32 * j);
        }
        #pragma unroll
        for (int off = 16; off; off >>= 1) {
            m  = fmaxf(m, __shfl_xor_sync(0xffffffffu, m, off));
            zs += __shfl_xor_sync(0xffffffffu, zs, off);
        }

        float tau = fmaxf(m - 1.0f, (zs - 1.0f) * (1.0f / (float)E));
        for (int it = 0; it < 64; it++) {
            float S = 0.f, K = 0.f;
            #pragma unroll
            for (int j = 0; j < 16; j++) {
                if (z[j] > tau) { S += z[j]; K += 1.0f; }
            }
            #pragma unroll
            for (int off = 16; off; off >>= 1) {
                S += __shfl_xor_sync(0xffffffffu, S, off);
                K += __shfl_xor_sync(0xffffffffu, K, off);
            }
            float tnew = (S - 1.0f) / K;
            if (!(tnew > tau)) break;
            tau = tnew;
        }

        float* om = out_masked + ((size_t)h * NROWS + n) * E;              // (H,B,T,E)
        float* ok = out_masks  + (((size_t)b * H + h) * 512 + t) * E;      // (B,H,T,E)
        #pragma unroll
        for (int j = 0; j < 16; j++) {
            const int o = lane + 32 * j;
            float mask = fmaxf(z[j] - tau, 0.0f);
            __stcs(om + o, xr[j] * mask);
            __stcs(ok + o, mask);
            prior[j] *= fmaxf(GAMMA - mask, 0.0f);
        }
    }
}

// ---------------------------------------------------------------------------
extern "C" void kernel_launch(void* const* d_in, const int* in_sizes, int n_in,
                              void* d_out, int out_size) {
    const float* x  = (const float*)d_in[0];
    const float* W  = (const float*)d_in[1];
    const float* bw = (const float*)d_in[2];
    const float* bb = (const float*)d_in[3];
    float* out_masked = (float*)d_out;                                  // (H,B,T,E)
    float* out_masks  = (float*)d_out + (size_t)H * NROWS * E;          // (B,H,T,E)

    cudaFuncSetAttribute(gemm_kernel, cudaFuncAttributeMaxDynamicSharedMemorySize, SMEM_TOTAL);

    split_kernel<<<XSPLIT_BLOCKS + WSPLIT_BLOCKS, 256>>>(x, W);

    dim3 ggrid(NROWS / BM, E / BN, H);
    gemm_kernel<<<ggrid, 256, SMEM_TOTAL>>>();

    finalize_kernel<<<dim3(H, 4), 512>>>(bw, bb);
    scan_kernel<<<NROWS / 8, 256>>>(x, out_masked, out_masks);
}